// round 1
// baseline (speedup 1.0000x reference)
#include <cuda_runtime.h>
#include <math.h>

typedef unsigned long long ULL;

// ---------------- static scratch (no allocations allowed) ----------------
__device__ __align__(16) float g_v[2 * 1024 * 64];      // vertex feats [B,N,64]
__device__ __align__(16) float g_f[2 * 2048 * 64];      // face feats   [B,F,64]
__device__ __align__(16) float g_X[2 * 4096 * 16];      // x2 buffer (= [B,N,64])
__device__ __align__(16) float g_Y[2 * 8192 * 16];      // y2 buffer (= [B,F,64])
__device__ __align__(16) float g_part[4194304];         // split-K partials (16 MB)
__device__ float g_sp[64 * 64];
__device__ float g_sq[64 * 64];
__device__ float g_a[64];
__device__ float g_c[64];
__device__ float g_pool[2 * 64];

// ---------------- helpers ----------------
__device__ __forceinline__ float elu1(float x) { return x > 0.f ? x : expm1f(x); }

__device__ __forceinline__ ULL pk2(float s) {
    ULL r; asm("mov.b64 %0, {%1, %1};" : "=l"(r) : "f"(s)); return r;
}
__device__ __forceinline__ void fma2(ULL& d, ULL a, ULL b) {
    asm("fma.rn.f32x2 %0, %1, %2, %0;" : "+l"(d) : "l"(a), "l"(b));
}

// ---------------- init kernels ----------------
__global__ void k_init_v(const float* __restrict__ inp,
                         const float* __restrict__ Win,
                         const float* __restrict__ bin,
                         float* __restrict__ v) {
    int idx = blockIdx.x * 256 + threadIdx.x;          // 2048*64 = 131072
    int r = idx >> 6, ch = idx & 63;
    float acc = bin[ch];
#pragma unroll
    for (int k = 0; k < 3; k++) acc = fmaf(inp[r * 3 + k], Win[k * 64 + ch], acc);
    v[idx] = acc;
}

__global__ void k_zero(float* __restrict__ p, int n) {
    int i = blockIdx.x * 256 + threadIdx.x;
    if (i < n) p[i] = 0.f;
}

// ---------------- BN stats (two-phase, deterministic) ----------------
__global__ void k_stats_part(const float* __restrict__ src, int rows) {
    __shared__ float ss[256], qq[256];
    int ch = threadIdx.x & 63, g = threadIdx.x >> 6;
    int slice = rows / gridDim.x;                       // gridDim.x = 64
    int r0 = blockIdx.x * slice;
    float s = 0.f, q = 0.f;
    for (int r = r0 + g; r < r0 + slice; r += 4) {
        float x = elu1(src[(size_t)r * 64 + ch]);
        s += x; q += x * x;
    }
    ss[threadIdx.x] = s; qq[threadIdx.x] = q;
    __syncthreads();
    if (g == 0) {
#pragma unroll
        for (int j = 1; j < 4; j++) { s += ss[ch + 64 * j]; q += qq[ch + 64 * j]; }
        g_sp[blockIdx.x * 64 + ch] = s;
        g_sq[blockIdx.x * 64 + ch] = q;
    }
}

__global__ void k_stats_final(const float* __restrict__ gamma,
                              const float* __restrict__ beta, float inv_count) {
    int ch = threadIdx.x;                               // 64 threads
    float s = 0.f, q = 0.f;
    for (int i = 0; i < 64; i++) { s += g_sp[i * 64 + ch]; q += g_sq[i * 64 + ch]; }
    float m = s * inv_count;
    float var = q * inv_count - m * m;
    float a = gamma[ch] * rsqrtf(var + 1e-5f);
    g_a[ch] = a;
    g_c[ch] = beta[ch] - m * a;
}

// ---------------- elu -> BN -> 64x64 linear -> elu ----------------
__global__ void __launch_bounds__(256) k_xform(const float* __restrict__ src,
                                               const float* __restrict__ W,
                                               const float* __restrict__ bias,
                                               float* __restrict__ dst, int rows) {
    __shared__ float Ws[64 * 64];
    __shared__ float ts[4 * 64];
    __shared__ float sa[64], sc[64], sb[64];
    for (int i = threadIdx.x; i < 4096; i += 256) Ws[i] = W[i];
    if (threadIdx.x < 64) {
        sa[threadIdx.x] = g_a[threadIdx.x];
        sc[threadIdx.x] = g_c[threadIdx.x];
        sb[threadIdx.x] = bias[threadIdx.x];
    }
    __syncthreads();
    int ch = threadIdx.x & 63, g = threadIdx.x >> 6;
    int rpb = rows / gridDim.x;                         // 16
    int base = blockIdx.x * rpb;
    for (int t = 0; t < rpb / 4; t++) {
        int r = base + t * 4 + g;
        float x = elu1(src[(size_t)r * 64 + ch]);
        ts[g * 64 + ch] = fmaf(x, sa[ch], sc[ch]);
        __syncthreads();
        float acc = sb[ch];
#pragma unroll
        for (int k = 0; k < 64; k++) acc = fmaf(ts[g * 64 + k], Ws[k * 64 + ch], acc);
        dst[(size_t)r * 64 + ch] = elu1(acc);
        __syncthreads();
    }
}

// ---------------- the big skinny GEMM: part[s] = D[rows, k-slice] @ X ----------------
// grid: (ksplit, M/256, B), block 128. kc = 256 always. Each thread: 2 rows.
__global__ void __launch_bounds__(128) k_gemm(const float* __restrict__ D,
                                              const float* __restrict__ X,
                                              float* __restrict__ part,
                                              int M, int K) {
    __shared__ __align__(16) float4 Xs[256 * 4];        // [k][16 floats], 16 KB
    int s = blockIdx.x, mt = blockIdx.y, b = blockIdx.z;
    int k0 = s * 256;
    const float4* xg = (const float4*)(X + ((size_t)b * K + k0) * 16);
    for (int i = threadIdx.x; i < 1024; i += 128) Xs[i] = xg[i];
    __syncthreads();

    int m1 = mt * 256 + threadIdx.x;
    const float4* p1 = (const float4*)(D + ((size_t)b * M + m1) * K + k0);
    const float4* p2 = (const float4*)(D + ((size_t)b * M + m1 + 128) * K + k0);
    const ulonglong2* xs = (const ulonglong2*)Xs;       // per k: 4 ulonglong2

    ULL a1[8], a2[8];
#pragma unroll
    for (int j = 0; j < 8; j++) { a1[j] = 0ULL; a2[j] = 0ULL; }

#pragma unroll 4
    for (int i = 0; i < 64; i++) {
        float4 d1 = p1[i];
        float4 d2 = p2[i];
#pragma unroll
        for (int q = 0; q < 4; q++) {
            int k = i * 4 + q;
            float v1 = (q == 0) ? d1.x : (q == 1) ? d1.y : (q == 2) ? d1.z : d1.w;
            float v2 = (q == 0) ? d2.x : (q == 1) ? d2.y : (q == 2) ? d2.z : d2.w;
            ULL w1 = pk2(v1);
            ULL w2 = pk2(v2);
#pragma unroll
            for (int j = 0; j < 4; j++) {
                ulonglong2 xv = xs[k * 4 + j];
                fma2(a1[2 * j],     w1, xv.x);
                fma2(a1[2 * j + 1], w1, xv.y);
                fma2(a2[2 * j],     w2, xv.x);
                fma2(a2[2 * j + 1], w2, xv.y);
            }
        }
    }
    size_t base = ((size_t)s * gridDim.z + b) * M;
    ULL* o1 = (ULL*)part + (base + m1) * 8;
    ULL* o2 = (ULL*)part + (base + m1 + 128) * 8;
#pragma unroll
    for (int j = 0; j < 8; j++) { o1[j] = a1[j]; o2[j] = a2[j]; }
}

// deterministic ordered split-K reduce:  out[i] += sum_s part[s][i]
__global__ void k_reduce(float4* __restrict__ out, const float4* __restrict__ part,
                         int n4, int ksplit) {
    int i = blockIdx.x * 256 + threadIdx.x;
    if (i >= n4) return;
    float4 a = out[i];
    for (int s = 0; s < ksplit; s++) {
        float4 p = part[(size_t)s * n4 + i];
        a.x += p.x; a.y += p.y; a.z += p.z; a.w += p.w;
    }
    out[i] = a;
}

// ---------------- epilogue ----------------
__global__ void k_pool(const float* __restrict__ t, const float* __restrict__ mask) {
    __shared__ float ss[256], ms[256];
    int b = blockIdx.x;
    int ch = threadIdx.x & 63, g = threadIdx.x >> 6;
    float s = 0.f, m = 0.f;
    for (int n = g; n < 1024; n += 4) {
        float mv = mask[b * 1024 + n];
        s += t[((size_t)b * 1024 + n) * 64 + ch] * mv;
        m += mv;
    }
    ss[threadIdx.x] = s; ms[threadIdx.x] = m;
    __syncthreads();
    if (g == 0) {
#pragma unroll
        for (int j = 1; j < 4; j++) { s += ss[ch + 64 * j]; m += ms[ch + 64 * j]; }
        g_pool[b * 64 + ch] = s / m;
    }
}

__global__ void k_head(const float* __restrict__ Wfc, const float* __restrict__ bfc,
                       float* __restrict__ out) {
    __shared__ float lg[2][10];
    int tid = threadIdx.x;
    if (tid < 20) {
        int b = tid / 10, j = tid % 10;
        float acc = bfc[j];
        for (int ch = 0; ch < 64; ch++) acc = fmaf(g_pool[b * 64 + ch], Wfc[ch * 10 + j], acc);
        lg[b][j] = acc;
    }
    __syncthreads();
    if (tid < 20) {
        int b = tid / 10, j = tid % 10;
        float mx = -1e30f;
        for (int t = 0; t < 10; t++) mx = fmaxf(mx, lg[b][t]);
        float se = 0.f;
        for (int t = 0; t < 10; t++) se += expf(lg[b][t] - mx);
        out[b * 10 + j] = lg[b][j] - mx - logf(se);
    }
}

// ---------------- launcher ----------------
extern "C" void kernel_launch(void* const* d_in, const int* in_sizes, int n_in,
                              void* d_out, int out_size) {
    const float* inp  = (const float*)d_in[0];
    const float* Di   = (const float*)d_in[1];
    const float* DiA  = (const float*)d_in[2];
    const float* mask = (const float*)d_in[3];
    const float* W_in = (const float*)d_in[4];
    const float* b_in = (const float*)d_in[5];
    const float* rnW0 = (const float*)d_in[6];
    const float* rnb0 = (const float*)d_in[7];
    const float* rng0 = (const float*)d_in[8];
    const float* rnbe0= (const float*)d_in[9];
    const float* rnW1 = (const float*)d_in[10];
    const float* rnb1 = (const float*)d_in[11];
    const float* rng1 = (const float*)d_in[12];
    const float* rnbe1= (const float*)d_in[13];
    const float* bn2g = (const float*)d_in[14];
    const float* bn2b = (const float*)d_in[15];
    const float* W2   = (const float*)d_in[16];
    const float* b2   = (const float*)d_in[17];
    const float* Wfc  = (const float*)d_in[18];
    const float* bfc  = (const float*)d_in[19];
    float* out = (float*)d_out;

    float *v, *f, *X, *Y, *part;
    cudaGetSymbolAddress((void**)&v, g_v);
    cudaGetSymbolAddress((void**)&f, g_f);
    cudaGetSymbolAddress((void**)&X, g_X);
    cudaGetSymbolAddress((void**)&Y, g_Y);
    cudaGetSymbolAddress((void**)&part, g_part);

    k_init_v<<<512, 256>>>(inp, W_in, b_in, v);
    k_zero<<<1024, 256>>>(f, 2 * 2048 * 64);

    for (int i = 0; i < 5; i++) {
        // vertex -> face
        k_stats_part<<<64, 256>>>(v, 2048);
        k_stats_final<<<1, 64>>>(rng0 + i * 64, rnbe0 + i * 64, 1.f / 2048.f);
        k_xform<<<128, 256>>>(v, rnW0 + i * 4096, rnb0 + i * 64, X, 2048);
        k_gemm<<<dim3(16, 32, 2), 128>>>(Di, X, part, 8192, 4096);
        k_reduce<<<256, 256>>>((float4*)f, (const float4*)part, 65536, 16);
        // face -> vertex
        k_stats_part<<<64, 256>>>(f, 4096);
        k_stats_final<<<1, 64>>>(rng1 + i * 64, rnbe1 + i * 64, 1.f / 4096.f);
        k_xform<<<256, 256>>>(f, rnW1 + i * 4096, rnb1 + i * 64, Y, 4096);
        k_gemm<<<dim3(32, 16, 2), 128>>>(DiA, Y, part, 4096, 8192);
        k_reduce<<<128, 256>>>((float4*)v, (const float4*)part, 32768, 32);
    }

    // epilogue: elu -> BN -> W2 -> elu -> masked mean pool -> fc -> log_softmax
    k_stats_part<<<64, 256>>>(v, 2048);
    k_stats_final<<<1, 64>>>(bn2g, bn2b, 1.f / 2048.f);
    k_xform<<<128, 256>>>(v, W2, b2, Y, 2048);
    k_pool<<<2, 256>>>(Y, mask);
    k_head<<<1, 32>>>(Wfc, bfc, out);
}